// round 2
// baseline (speedup 1.0000x reference)
#include <cuda_runtime.h>

#define SS 9
#define FF 32

constexpr int N_MAX = 16384;
constexpr int E_MAX = 524288;

// Device scratch (static allocation — no runtime allocs allowed)
__device__ int g_count[N_MAX];
__device__ int g_offset[N_MAX + 1];
__device__ int g_cursor[N_MAX];
__device__ int g_edges[E_MAX];

__device__ __forceinline__ float envelope_f(float d) {
    float u = fminf(fmaxf(d, 0.0f), 1.0f);
    float u2 = u * u;
    float u4 = u2 * u2;
    float u5 = u4 * u;
    // 1 - 21 u^5 + 35 u^6 - 15 u^7
    return 1.0f + u5 * (-21.0f + u * (35.0f - 15.0f * u));
}

__global__ void zero_counts(int n) {
    int i = blockIdx.x * blockDim.x + threadIdx.x;
    if (i < n) g_count[i] = 0;
}

__global__ void hist_kernel(const int* __restrict__ ei, int e_cnt) {
    int i = blockIdx.x * blockDim.x + threadIdx.x;
    if (i < e_cnt) atomicAdd(&g_count[ei[e_cnt + i]], 1);
}

// Single-block exclusive scan over g_count -> g_offset, g_cursor
__global__ void scan_kernel(int n) {
    __shared__ int part[1024];
    int tid = threadIdx.x;
    int ch = (n + 1023) >> 10;
    int base = tid * ch;
    int s = 0;
    for (int i = 0; i < ch; i++) {
        int idx = base + i;
        if (idx < n) s += g_count[idx];
    }
    part[tid] = s;
    __syncthreads();
    for (int off = 1; off < 1024; off <<= 1) {
        int v = (tid >= off) ? part[tid - off] : 0;
        __syncthreads();
        part[tid] += v;
        __syncthreads();
    }
    int run = (tid > 0) ? part[tid - 1] : 0;
    for (int i = 0; i < ch; i++) {
        int idx = base + i;
        if (idx < n) {
            g_offset[idx] = run;
            g_cursor[idx] = run;
            run += g_count[idx];
        }
    }
    if (tid == 1023) g_offset[n] = part[1023];
}

__global__ void scatter_kernel(const int* __restrict__ ei, int e_cnt) {
    int i = blockIdx.x * blockDim.x + threadIdx.x;
    if (i < e_cnt) {
        int d = ei[e_cnt + i];
        int pos = atomicAdd(&g_cursor[d], 1);
        g_edges[pos] = i;
    }
}

// One warp per destination node; lane = feature index f (F == 32).
__global__ __launch_bounds__(256) void aggregate_kernel(
    const float* __restrict__ x,
    const int*   __restrict__ ei,
    const float* __restrict__ ea,
    const float* __restrict__ cgg,
    const float* __restrict__ Wsca,
    const float* __restrict__ Wsph,
    const float* __restrict__ Wmix,
    float* __restrict__ out,
    int n, int e_cnt)
{
    // cg rows (p,q,·) padded to 12 floats for vectorized smem reads
    __shared__ __align__(16) float cgs[81 * 12];
    __shared__ __align__(16) float s_ys[8][12];
    __shared__ __align__(16) float s_aw[8][9 * 12];
    __shared__ float s_ww[96];   // W_sca * W_sph, [l*32 + f]
    __shared__ float s_wm[96];   // W_mix

    int tid = threadIdx.x;

    for (int t = tid; t < 729; t += 256) {
        int pq = t / 9;
        int r  = t - pq * 9;
        cgs[pq * 12 + r] = cgg[t];
    }
    for (int t = tid; t < 96; t += 256) {
        s_ww[t] = Wsca[t] * Wsph[t];
        s_wm[t] = Wmix[t];
    }
    __syncthreads();

    int w    = tid >> 5;
    int lane = tid & 31;
    int node = blockIdx.x * 8 + w;
    if (node >= n) return;

    const int lv[SS] = {0, 1, 1, 1, 2, 2, 2, 2, 2};

    float wwl[3], wml[3];
#pragma unroll
    for (int l = 0; l < 3; l++) {
        wwl[l] = s_ww[l * 32 + lane];
        wml[l] = s_wm[l * 32 + lane];
    }

    float acc[SS];
#pragma unroll
    for (int p = 0; p < SS; p++) acc[p] = 0.0f;

    int start = g_offset[node];
    int end   = g_offset[node + 1];

    float* ys = s_ys[w];
    float* aw = s_aw[w];

    for (int i = start; i < end; ++i) {
        int e    = g_edges[i];
        int srcn = ei[e];  // edge_index[0][e]

        // Lanes 0..8 fetch Y[s], lane 9 fetches d (broadcast across s by construction)
        if (lane < 10) {
            const long eb = (long)e * 18;
            int off = (lane < 9) ? (int)(eb + 2 * lane) : (int)(eb + 1);
            ys[(lane < 9) ? lane : 9] = ea[off];
        }
        __syncwarp();

        const float4 y0 = *(const float4*)(ys);
        const float4 y1 = *(const float4*)(ys + 4);
        const float4 y2 = *(const float4*)(ys + 8);
        float ya[SS] = {y0.x, y0.y, y0.z, y0.w, y1.x, y1.y, y1.z, y1.w, y2.x};
        float dd = y2.y;
        float env_d  = envelope_f(dd);
        float env_y0 = envelope_f(ya[0]);

        // A[p,q] = sum_r cg[p,q,r] * Y[r], distributed ~3 entries/lane
        for (int k = lane; k < 81; k += 32) {
            const float4 c0 = *(const float4*)(cgs + k * 12);
            const float4 c1 = *(const float4*)(cgs + k * 12 + 4);
            const float4 c2 = *(const float4*)(cgs + k * 12 + 8);
            float a = c0.x * ya[0] + c0.y * ya[1] + c0.z * ya[2] + c0.w * ya[3]
                    + c1.x * ya[4] + c1.y * ya[5] + c1.z * ya[6] + c1.w * ya[7]
                    + c2.x * ya[8];
            int p = k / 9;
            int q = k - p * 9;
            aw[p * 12 + q] = a;
        }
        __syncwarp();

        // Gather x_j for this lane's feature (coalesced: 32 lanes = 128B lines)
        const float* xb = x + (size_t)srcn * (SS * FF) + lane;
        float xq[SS];
#pragma unroll
        for (int q = 0; q < SS; q++) xq[q] = xb[q * FF];

#pragma unroll
        for (int p = 0; p < SS; p++) {
            const float4 a0 = *(const float4*)(aw + p * 12);
            const float4 a1 = *(const float4*)(aw + p * 12 + 4);
            const float4 a2 = *(const float4*)(aw + p * 12 + 8);
            float mixed = a0.x * xq[0] + a0.y * xq[1] + a0.z * xq[2] + a0.w * xq[3]
                        + a1.x * xq[4] + a1.y * xq[5] + a1.z * xq[6] + a1.w * xq[7]
                        + a2.x * xq[8];
            acc[p] += xq[p] * (env_d * ya[p]) * wwl[lv[p]]
                    + (env_y0 * wml[lv[p]]) * mixed;
        }
        __syncwarp();
    }

    // out = x + aggr (single writer per element; also covers degree-0 nodes)
    const float* xn = x   + (size_t)node * (SS * FF) + lane;
    float*       on = out + (size_t)node * (SS * FF) + lane;
#pragma unroll
    for (int p = 0; p < SS; p++) on[p * FF] = xn[p * FF] + acc[p];
}

extern "C" void kernel_launch(void* const* d_in, const int* in_sizes, int n_in,
                              void* d_out, int out_size)
{
    const float* x    = (const float*)d_in[0];
    const int*   ei   = (const int*)  d_in[1];
    const float* ea   = (const float*)d_in[2];
    const float* wsca = (const float*)d_in[3];
    const float* wsph = (const float*)d_in[4];
    const float* wmix = (const float*)d_in[5];
    const float* cgg  = (const float*)d_in[6];
    float* out = (float*)d_out;

    int n = in_sizes[0] / (SS * FF);
    int e = in_sizes[1] / 2;

    zero_counts<<<(n + 255) / 256, 256>>>(n);
    hist_kernel<<<(e + 255) / 256, 256>>>(ei, e);
    scan_kernel<<<1, 1024>>>(n);
    scatter_kernel<<<(e + 255) / 256, 256>>>(ei, e);
    aggregate_kernel<<<(n + 7) / 8, 256>>>(x, ei, ea, cgg, wsca, wsph, wmix, out, n, e);
}

// round 3
// speedup vs baseline: 1.1559x; 1.1559x over previous
#include <cuda_runtime.h>

#define SS 9
#define FF 32

constexpr int N_MAX = 16384;
constexpr int E_MAX = 524288;

__device__ int g_count[N_MAX];
__device__ int g_offset[N_MAX + 1];
__device__ int g_cursor[N_MAX];
__device__ int g_edges[E_MAX];

__device__ __forceinline__ float envelope_f(float d) {
    float u = fminf(fmaxf(d, 0.0f), 1.0f);
    float u2 = u * u;
    float u4 = u2 * u2;
    float u5 = u4 * u;
    return 1.0f + u5 * (-21.0f + u * (35.0f - 15.0f * u));
}

__global__ void zero_counts(int n) {
    int i = blockIdx.x * blockDim.x + threadIdx.x;
    if (i < n) g_count[i] = 0;
}

__global__ void hist_kernel(const int* __restrict__ ei, int e_cnt) {
    int i = blockIdx.x * blockDim.x + threadIdx.x;
    if (i < e_cnt) atomicAdd(&g_count[ei[e_cnt + i]], 1);
}

__global__ void scan_kernel(int n) {
    __shared__ int part[1024];
    int tid = threadIdx.x;
    int ch = (n + 1023) >> 10;
    int base = tid * ch;
    int s = 0;
    for (int i = 0; i < ch; i++) {
        int idx = base + i;
        if (idx < n) s += g_count[idx];
    }
    part[tid] = s;
    __syncthreads();
    for (int off = 1; off < 1024; off <<= 1) {
        int v = (tid >= off) ? part[tid - off] : 0;
        __syncthreads();
        part[tid] += v;
        __syncthreads();
    }
    int run = (tid > 0) ? part[tid - 1] : 0;
    for (int i = 0; i < ch; i++) {
        int idx = base + i;
        if (idx < n) {
            g_offset[idx] = run;
            g_cursor[idx] = run;
            run += g_count[idx];
        }
    }
    if (tid == 1023) g_offset[n] = part[1023];
}

__global__ void scatter_kernel(const int* __restrict__ ei, int e_cnt) {
    int i = blockIdx.x * blockDim.x + threadIdx.x;
    if (i < e_cnt) {
        int d = ei[e_cnt + i];
        int pos = atomicAdd(&g_cursor[d], 1);
        g_edges[pos] = i;
    }
}

// One warp per destination node; lane = feature index f (F == 32).
// cg rows live in loop-invariant registers (3 rows/lane). A matrix goes
// through double-buffered smem (1 syncwarp/edge). x and Y for edge i+1 are
// prefetched past the compute of edge i.
__global__ __launch_bounds__(256, 2) void aggregate_kernel(
    const float* __restrict__ x,
    const int*   __restrict__ ei,
    const float* __restrict__ ea,
    const float* __restrict__ cgg,
    const float* __restrict__ Wsca,
    const float* __restrict__ Wsph,
    const float* __restrict__ Wmix,
    float* __restrict__ out,
    int n, int e_cnt)
{
    __shared__ __align__(16) float s_aw[8][2][112];  // 9 rows x 12 (padded), double buffered

    int tid  = threadIdx.x;
    int w    = tid >> 5;
    int lane = tid & 31;
    int node = blockIdx.x * 8 + w;
    if (node >= n) return;

    const int lv[SS] = {0, 1, 1, 1, 2, 2, 2, 2, 2};

    // Per-lane weights (broadcast global reads, once)
    float wwl[3], wml[3];
#pragma unroll
    for (int l = 0; l < 3; l++) {
        wwl[l] = Wsca[l * 32 + lane] * Wsph[l * 32 + lane];
        wml[l] = Wmix[l * 32 + lane];
    }

    // Loop-invariant cg rows for this lane's k in {lane, lane+32, lane+64}
    float cgr[3][9];
    int   saddr[3];
    bool  valid[3];
#pragma unroll
    for (int j = 0; j < 3; j++) {
        int k = lane + j * 32;
        valid[j] = (k < 81);
        int kk = valid[j] ? k : 0;
        int p = kk / 9, q = kk - p * 9;
        saddr[j] = p * 12 + q;
#pragma unroll
        for (int r = 0; r < 9; r++) cgr[j][r] = cgg[kk * 9 + r];
    }

    float acc[SS];
#pragma unroll
    for (int p = 0; p < SS; p++) acc[p] = 0.0f;

    int start = g_offset[node];
    int end   = g_offset[node + 1];

    const float2* __restrict__ ea2 = (const float2*)ea;  // (E, 9) of (Y_s, d)

    float xq[SS], xqn[SS];
    float ya[SS], yan[SS];
    float dd = 0.0f, ddn = 0.0f;

    // Prologue: load edge 'start'
    if (start < end) {
        int e0 = g_edges[start];
        int s0 = ei[e0];
        const float* xb = x + (size_t)s0 * (SS * FF) + lane;
#pragma unroll
        for (int q = 0; q < SS; q++) xq[q] = xb[q * FF];
        const float2* yb = ea2 + (size_t)e0 * SS;
#pragma unroll
        for (int s = 0; s < SS; s++) {
            float2 v = yb[s];
            ya[s] = v.x;
            if (s == 0) dd = v.y;
        }
    }

    int buf = 0;
    for (int i = start; i < end; ++i) {
        // ---- kick off prefetch of edge i+1 (clamped) ----
        int inx = (i + 1 < end) ? (i + 1) : i;
        int en  = g_edges[inx];
        int sn  = ei[en];
        const float* xbn = x + (size_t)sn * (SS * FF) + lane;
        const float2* ybn = ea2 + (size_t)en * SS;

        // ---- A build from registers (current edge) ----
        float* awb = s_aw[w][buf];
#pragma unroll
        for (int j = 0; j < 3; j++) {
            float a = cgr[j][0] * ya[0];
#pragma unroll
            for (int r = 1; r < 9; r++) a = fmaf(cgr[j][r], ya[r], a);
            if (valid[j]) awb[saddr[j]] = a;
        }
        __syncwarp();

        // ---- issue next-edge loads (overlap with p-loop below) ----
#pragma unroll
        for (int q = 0; q < SS; q++) xqn[q] = xbn[q * FF];
#pragma unroll
        for (int s = 0; s < SS; s++) {
            float2 v = ybn[s];
            yan[s] = v.x;
            if (s == 0) ddn = v.y;
        }

        // ---- per-edge coefficients ----
        float env_d  = envelope_f(dd);
        float env_y0 = envelope_f(ya[0]);
        float gm[3];
#pragma unroll
        for (int l = 0; l < 3; l++) gm[l] = env_y0 * wml[l];
        float cpa[SS];
#pragma unroll
        for (int p = 0; p < SS; p++) cpa[p] = env_d * ya[p] * wwl[lv[p]];

        // ---- p-loop: mixed matvec + gated sum ----
#pragma unroll
        for (int p = 0; p < SS; p++) {
            const float4 a0 = *(const float4*)(awb + p * 12);
            const float4 a1 = *(const float4*)(awb + p * 12 + 4);
            const float  a8 = awb[p * 12 + 8];
            float mixed = a0.x * xq[0];
            mixed = fmaf(a0.y, xq[1], mixed);
            mixed = fmaf(a0.z, xq[2], mixed);
            mixed = fmaf(a0.w, xq[3], mixed);
            mixed = fmaf(a1.x, xq[4], mixed);
            mixed = fmaf(a1.y, xq[5], mixed);
            mixed = fmaf(a1.z, xq[6], mixed);
            mixed = fmaf(a1.w, xq[7], mixed);
            mixed = fmaf(a8,   xq[8], mixed);
            acc[p] = fmaf(xq[p], cpa[p], acc[p]);
            acc[p] = fmaf(gm[lv[p]], mixed, acc[p]);
        }

        // ---- rotate prefetch -> current ----
#pragma unroll
        for (int q = 0; q < SS; q++) xq[q] = xqn[q];
#pragma unroll
        for (int s = 0; s < SS; s++) ya[s] = yan[s];
        dd = ddn;
        buf ^= 1;
    }

    const float* xn = x   + (size_t)node * (SS * FF) + lane;
    float*       on = out + (size_t)node * (SS * FF) + lane;
#pragma unroll
    for (int p = 0; p < SS; p++) on[p * FF] = xn[p * FF] + acc[p];
}

extern "C" void kernel_launch(void* const* d_in, const int* in_sizes, int n_in,
                              void* d_out, int out_size)
{
    const float* x    = (const float*)d_in[0];
    const int*   ei   = (const int*)  d_in[1];
    const float* ea   = (const float*)d_in[2];
    const float* wsca = (const float*)d_in[3];
    const float* wsph = (const float*)d_in[4];
    const float* wmix = (const float*)d_in[5];
    const float* cgg  = (const float*)d_in[6];
    float* out = (float*)d_out;

    int n = in_sizes[0] / (SS * FF);
    int e = in_sizes[1] / 2;

    zero_counts<<<(n + 255) / 256, 256>>>(n);
    hist_kernel<<<(e + 255) / 256, 256>>>(ei, e);
    scan_kernel<<<1, 1024>>>(n);
    scatter_kernel<<<(e + 255) / 256, 256>>>(ei, e);
    aggregate_kernel<<<(n + 7) / 8, 256>>>(x, ei, ea, cgg, wsca, wsph, wmix, out, n, e);
}

// round 5
// speedup vs baseline: 1.2471x; 1.0789x over previous
#include <cuda_runtime.h>

#define SS 9
#define FF 32

constexpr int N_MAX = 16384;
constexpr int E_MAX = 524288;

__device__ int g_count[N_MAX];
__device__ int g_offset[N_MAX + 1];
__device__ int g_cursor[N_MAX];
__device__ int g_edges[E_MAX];

typedef unsigned long long u64t;

__device__ __forceinline__ u64t pk2(float lo, float hi) {
    u64t r;
    asm("mov.b64 %0, {%1,%2};" : "=l"(r) : "f"(lo), "f"(hi));
    return r;
}
__device__ __forceinline__ void upk2(u64t v, float& lo, float& hi) {
    asm("mov.b64 {%0,%1}, %2;" : "=f"(lo), "=f"(hi) : "l"(v));
}
__device__ __forceinline__ u64t fma2(u64t a, u64t b, u64t c) {
    u64t d;
    asm("fma.rn.f32x2 %0, %1, %2, %3;" : "=l"(d) : "l"(a), "l"(b), "l"(c));
    return d;
}
__device__ __forceinline__ u64t mul2(u64t a, u64t b) {
    u64t d;
    asm("mul.rn.f32x2 %0, %1, %2;" : "=l"(d) : "l"(a), "l"(b));
    return d;
}

__device__ __forceinline__ float envelope_f(float d) {
    float u = fminf(fmaxf(d, 0.0f), 1.0f);
    float u2 = u * u;
    float u4 = u2 * u2;
    float u5 = u4 * u;
    return 1.0f + u5 * (-21.0f + u * (35.0f - 15.0f * u));
}

__global__ void zero_counts(int n) {
    int i = blockIdx.x * blockDim.x + threadIdx.x;
    if (i < n) g_count[i] = 0;
}

__global__ void hist_kernel(const int* __restrict__ ei, int e_cnt) {
    int i = blockIdx.x * blockDim.x + threadIdx.x;
    if (i < e_cnt) atomicAdd(&g_count[ei[e_cnt + i]], 1);
}

__global__ void scan_kernel(int n) {
    __shared__ int part[1024];
    int tid = threadIdx.x;
    int ch = (n + 1023) >> 10;
    int base = tid * ch;
    int s = 0;
    for (int i = 0; i < ch; i++) {
        int idx = base + i;
        if (idx < n) s += g_count[idx];
    }
    part[tid] = s;
    __syncthreads();
    for (int off = 1; off < 1024; off <<= 1) {
        int v = (tid >= off) ? part[tid - off] : 0;
        __syncthreads();
        part[tid] += v;
        __syncthreads();
    }
    int run = (tid > 0) ? part[tid - 1] : 0;
    for (int i = 0; i < ch; i++) {
        int idx = base + i;
        if (idx < n) {
            g_offset[idx] = run;
            g_cursor[idx] = run;
            run += g_count[idx];
        }
    }
    if (tid == 1023) g_offset[n] = part[1023];
}

__global__ void scatter_kernel(const int* __restrict__ ei, int e_cnt) {
    int i = blockIdx.x * blockDim.x + threadIdx.x;
    if (i < e_cnt) {
        int d = ei[e_cnt + i];
        int pos = atomicAdd(&g_cursor[d], 1);
        g_edges[pos] = i;
    }
}

// One warp per destination node; lane = feature f (F == 32).
// cg rows in registers; A stored into smem PAIR-INTERLEAVED:
//   p<8:  (A[2i][q], A[2i+1][q]) at floats [i*24 + 2q], i = p>>1
//   p==8: A[8][q] at floats [96 + q]
// so the mixed matvec runs on packed fma.rn.f32x2 (FFMA2, 2 flops/issue).
__global__ __launch_bounds__(128) void aggregate_kernel(
    const float* __restrict__ x,
    const int*   __restrict__ ei,
    const float* __restrict__ ea,
    const float* __restrict__ cgg,
    const float* __restrict__ Wsca,
    const float* __restrict__ Wsph,
    const float* __restrict__ Wmix,
    float* __restrict__ out,
    int n, int e_cnt)
{
    __shared__ __align__(16) float s_aw[4][2][112];  // [warp][buf][pair-interleaved A]

    int tid  = threadIdx.x;
    int w    = tid >> 5;
    int lane = tid & 31;
    int node = blockIdx.x * 4 + w;
    if (node >= n) return;

    const int lv[SS] = {0, 1, 1, 1, 2, 2, 2, 2, 2};

    float wwl[3], wml[3];
#pragma unroll
    for (int l = 0; l < 3; l++) {
        wwl[l] = Wsca[l * 32 + lane] * Wsph[l * 32 + lane];
        wml[l] = Wmix[l * 32 + lane];
    }

    // Loop-invariant cg rows: lane owns k in {lane, lane+32, lane+64}
    float cgr[3][9];
    int   saddr[3];
    bool  valid[3];
#pragma unroll
    for (int j = 0; j < 3; j++) {
        int k = lane + j * 32;
        valid[j] = (k < 81);
        int kk = valid[j] ? k : 0;
        int p = kk / 9, q = kk - p * 9;
        // pair-interleaved target address
        saddr[j] = (p < 8) ? ((p >> 1) * 24 + q * 2 + (p & 1)) : (96 + q);
#pragma unroll
        for (int r = 0; r < 9; r++) cgr[j][r] = cgg[kk * 9 + r];
    }

    u64t acc2[4];
#pragma unroll
    for (int i = 0; i < 4; i++) acc2[i] = 0ull;
    float acc8 = 0.0f;

    int start = g_offset[node];
    int end   = g_offset[node + 1];

    const float2* __restrict__ ea2 = (const float2*)ea;

    float xq[SS], xqn[SS];
    float ya[SS], yan[SS];
    float dd = 0.0f, ddn = 0.0f;

    if (start < end) {
        int e0 = g_edges[start];
        int s0 = ei[e0];
        const float* xb = x + (size_t)s0 * (SS * FF) + lane;
#pragma unroll
        for (int q = 0; q < SS; q++) xq[q] = xb[q * FF];
        const float2* yb = ea2 + (size_t)e0 * SS;
#pragma unroll
        for (int s = 0; s < SS; s++) {
            float2 v = yb[s];
            ya[s] = v.x;
            if (s == 0) dd = v.y;
        }
    }

    int buf = 0;
    for (int i = start; i < end; ++i) {
        int inx = (i + 1 < end) ? (i + 1) : i;
        int en  = g_edges[inx];
        int sn  = ei[en];
        const float* xbn  = x + (size_t)sn * (SS * FF) + lane;
        const float2* ybn = ea2 + (size_t)en * SS;

        // ---- A build (scalar FFMA), store pair-interleaved ----
        float* awb = s_aw[w][buf];
#pragma unroll
        for (int j = 0; j < 3; j++) {
            float a = cgr[j][0] * ya[0];
#pragma unroll
            for (int r = 1; r < 9; r++) a = fmaf(cgr[j][r], ya[r], a);
            if (valid[j]) awb[saddr[j]] = a;
        }
        __syncwarp();

        // ---- prefetch next edge (overlaps compute below) ----
#pragma unroll
        for (int q = 0; q < SS; q++) xqn[q] = xbn[q * FF];
#pragma unroll
        for (int s = 0; s < SS; s++) {
            float2 v = ybn[s];
            yan[s] = v.x;
            if (s == 0) ddn = v.y;
        }

        // ---- per-edge coefficients (packed) ----
        float env_d  = envelope_f(dd);
        float env_y0 = envelope_f(ya[0]);
        float gml[3];
#pragma unroll
        for (int l = 0; l < 3; l++) gml[l] = env_y0 * wml[l];
        u64t gm2[4];
        gm2[0] = pk2(gml[0], gml[1]);
        gm2[1] = pk2(gml[1], gml[1]);
        gm2[2] = pk2(gml[2], gml[2]);
        gm2[3] = gm2[2];

        float cpa[SS];
#pragma unroll
        for (int p = 0; p < SS; p++) cpa[p] = env_d * ya[p] * wwl[lv[p]];
        u64t cpa2[4];
#pragma unroll
        for (int i2 = 0; i2 < 4; i2++) cpa2[i2] = pk2(cpa[2 * i2], cpa[2 * i2 + 1]);

        // duplicated-x pairs for packed matvec; adjacent-x pairs for msg_a
        u64t xq2[SS], xp2[4];
#pragma unroll
        for (int q = 0; q < SS; q++) xq2[q] = pk2(xq[q], xq[q]);
#pragma unroll
        for (int i2 = 0; i2 < 4; i2++) xp2[i2] = pk2(xq[2 * i2], xq[2 * i2 + 1]);

        // ---- packed mixed matvec over 4 p-pairs ----
#pragma unroll
        for (int pr = 0; pr < 4; pr++) {
            const float* rb = awb + pr * 24;
            const ulonglong2 u0 = *(const ulonglong2*)(rb);        // pairs q0,q1
            const ulonglong2 u1 = *(const ulonglong2*)(rb + 4);    // q2,q3
            const ulonglong2 u2 = *(const ulonglong2*)(rb + 8);    // q4,q5
            const ulonglong2 u3 = *(const ulonglong2*)(rb + 12);   // q6,q7
            const u64t       u4 = *(const u64t*)(rb + 16);         // q8
            u64t m = mul2(u0.x, xq2[0]);
            m = fma2(u0.y, xq2[1], m);
            m = fma2(u1.x, xq2[2], m);
            m = fma2(u1.y, xq2[3], m);
            m = fma2(u2.x, xq2[4], m);
            m = fma2(u2.y, xq2[5], m);
            m = fma2(u3.x, xq2[6], m);
            m = fma2(u3.y, xq2[7], m);
            m = fma2(u4,   xq2[8], m);
            acc2[pr] = fma2(xp2[pr], cpa2[pr], acc2[pr]);
            acc2[pr] = fma2(gm2[pr], m,        acc2[pr]);
        }
        // ---- scalar p = 8 row ----
        {
            const float* a8 = awb + 96;
            float m = a8[0] * xq[0];
#pragma unroll
            for (int q = 1; q < SS; q++) m = fmaf(a8[q], xq[q], m);
            acc8 = fmaf(xq[8], cpa[8], acc8);
            acc8 = fmaf(gml[2], m, acc8);
        }

        // ---- rotate prefetch ----
#pragma unroll
        for (int q = 0; q < SS; q++) xq[q] = xqn[q];
#pragma unroll
        for (int s = 0; s < SS; s++) ya[s] = yan[s];
        dd = ddn;
        buf ^= 1;
    }

    const float* xn = x   + (size_t)node * (SS * FF) + lane;
    float*       on = out + (size_t)node * (SS * FF) + lane;
#pragma unroll
    for (int pr = 0; pr < 4; pr++) {
        float lo, hi;
        upk2(acc2[pr], lo, hi);
        on[(2 * pr)     * FF] = xn[(2 * pr)     * FF] + lo;
        on[(2 * pr + 1) * FF] = xn[(2 * pr + 1) * FF] + hi;
    }
    on[8 * FF] = xn[8 * FF] + acc8;
}

extern "C" void kernel_launch(void* const* d_in, const int* in_sizes, int n_in,
                              void* d_out, int out_size)
{
    const float* x    = (const float*)d_in[0];
    const int*   ei   = (const int*)  d_in[1];
    const float* ea   = (const float*)d_in[2];
    const float* wsca = (const float*)d_in[3];
    const float* wsph = (const float*)d_in[4];
    const float* wmix = (const float*)d_in[5];
    const float* cgg  = (const float*)d_in[6];
    float* out = (float*)d_out;

    int n = in_sizes[0] / (SS * FF);
    int e = in_sizes[1] / 2;

    zero_counts<<<(n + 255) / 256, 256>>>(n);
    hist_kernel<<<(e + 255) / 256, 256>>>(ei, e);
    scan_kernel<<<1, 1024>>>(n);
    scatter_kernel<<<(e + 255) / 256, 256>>>(ei, e);
    aggregate_kernel<<<(n + 3) / 4, 128>>>(x, ei, ea, cgg, wsca, wsph, wmix, out, n, e);
}